// round 2
// baseline (speedup 1.0000x reference)
#include <cuda_runtime.h>
#include <cuda_bf16.h>
#include <math.h>

// Problem shape (fixed by the dataset): B=4, T=2048, D=512, H=8, Hd=64, FFN=2048
#define T_SEQ   2048
#define DIM     512
#define NHEAD   8
#define HDIM    64
#define FFN_DIM 2048
#define MAX_BT  8192

// ---------------- scratch (no cudaMalloc allowed) ----------------
__device__ float g_xn  [MAX_BT * DIM];        // rmsnorm output (reused)
__device__ float g_qkv [MAX_BT * 3 * DIM];    // qkv projections
__device__ float g_ctx [MAX_BT * DIM];        // attention context (pre out-proj)
__device__ float g_x1  [MAX_BT * DIM];        // x after attention residual
__device__ float g_h   [MAX_BT * FFN_DIM];    // FFN hidden

// ---------------- rmsnorm: one block per row (512 floats) ----------------
__global__ void rmsnorm_kernel(const float* __restrict__ x,
                               const float* __restrict__ w,
                               float* __restrict__ y) {
    const int row = blockIdx.x;
    const int tid = threadIdx.x;            // 128 threads
    const float4 v = reinterpret_cast<const float4*>(x + (size_t)row * DIM)[tid];
    float ss = v.x * v.x + v.y * v.y + v.z * v.z + v.w * v.w;
    #pragma unroll
    for (int off = 16; off > 0; off >>= 1)
        ss += __shfl_xor_sync(0xFFFFFFFFu, ss, off);
    __shared__ float red[4];
    const int warp = tid >> 5, lane = tid & 31;
    if (lane == 0) red[warp] = ss;
    __syncthreads();
    const float total = red[0] + red[1] + red[2] + red[3];
    const float r = rsqrtf(total * (1.0f / DIM) + 1e-6f);
    const float4 wv = reinterpret_cast<const float4*>(w)[tid];
    float4 o;
    o.x = v.x * r * wv.x;
    o.y = v.y * r * wv.y;
    o.z = v.z * r * wv.z;
    o.w = v.w * r * wv.w;
    reinterpret_cast<float4*>(y + (size_t)row * DIM)[tid] = o;
}

// ---------------- 128x128 SGEMM: C = A(MxK) * B(KxN) [+ bias][+ resid][gelu] ----------------
// EPI: 0 = none, 1 = bias + residual, 2 = bias + exact gelu
// 256 threads, 8x8 per thread, K-slab = 8, register prefetch of next slab.
// Requires M%128==0, N%128==0, K%8==0 (true for all shapes here).
template <int EPI>
__global__ __launch_bounds__(256, 2)
void gemm_kernel(const float* __restrict__ A,
                 const float* __restrict__ B,
                 const float* __restrict__ bias,
                 const float* __restrict__ R,
                 float* __restrict__ C,
                 int M, int N, int K) {
    __shared__ float As[8][128];   // transposed: As[k][m]
    __shared__ float Bs[8][128];   // Bs[k][n]
    const int bm = blockIdx.y * 128;
    const int bn = blockIdx.x * 128;
    const int tid = threadIdx.x;           // 256 threads

    // loader indices
    const int arow = tid >> 1;             // 0..127 (row within A tile)
    const int ak   = (tid & 1) * 4;        // 0 or 4
    const int brow = tid >> 5;             // 0..7   (k within B slab)
    const int bcol = (tid & 31) * 4;       // 0..124

    // compute indices
    const int tx = (tid & 15) * 8;         // col offset within tile
    const int ty = (tid >> 4) * 8;         // row offset within tile

    const float* Aptr = A + (size_t)(bm + arow) * K + ak;
    const float* Bptr = B + (size_t)brow * N + bn + bcol;

    float acc[8][8] = {};
    float4 pa = *reinterpret_cast<const float4*>(Aptr);
    float4 pb = *reinterpret_cast<const float4*>(Bptr);

    for (int k0 = 0; k0 < K; k0 += 8) {
        As[ak + 0][arow] = pa.x;
        As[ak + 1][arow] = pa.y;
        As[ak + 2][arow] = pa.z;
        As[ak + 3][arow] = pa.w;
        *reinterpret_cast<float4*>(&Bs[brow][bcol]) = pb;
        __syncthreads();

        if (k0 + 8 < K) {
            pa = *reinterpret_cast<const float4*>(Aptr + k0 + 8);
            pb = *reinterpret_cast<const float4*>(Bptr + (size_t)(k0 + 8) * N);
        }

        #pragma unroll
        for (int k = 0; k < 8; ++k) {
            float ar[8], br[8];
            const float4 a0 = *reinterpret_cast<const float4*>(&As[k][ty]);
            const float4 a1 = *reinterpret_cast<const float4*>(&As[k][ty + 4]);
            const float4 b0 = *reinterpret_cast<const float4*>(&Bs[k][tx]);
            const float4 b1 = *reinterpret_cast<const float4*>(&Bs[k][tx + 4]);
            ar[0]=a0.x; ar[1]=a0.y; ar[2]=a0.z; ar[3]=a0.w;
            ar[4]=a1.x; ar[5]=a1.y; ar[6]=a1.z; ar[7]=a1.w;
            br[0]=b0.x; br[1]=b0.y; br[2]=b0.z; br[3]=b0.w;
            br[4]=b1.x; br[5]=b1.y; br[6]=b1.z; br[7]=b1.w;
            #pragma unroll
            for (int i = 0; i < 8; ++i)
                #pragma unroll
                for (int j = 0; j < 8; ++j)
                    acc[i][j] = fmaf(ar[i], br[j], acc[i][j]);
        }
        __syncthreads();
    }

    // epilogue
    #pragma unroll
    for (int i = 0; i < 8; ++i) {
        const int row = bm + ty + i;
        #pragma unroll
        for (int jj = 0; jj < 2; ++jj) {
            const int col = bn + tx + jj * 4;
            float v[4] = {acc[i][jj*4+0], acc[i][jj*4+1], acc[i][jj*4+2], acc[i][jj*4+3]};
            if (EPI == 1) {
                const float4 rv = *reinterpret_cast<const float4*>(R + (size_t)row * N + col);
                v[0] += bias[col + 0] + rv.x;
                v[1] += bias[col + 1] + rv.y;
                v[2] += bias[col + 2] + rv.z;
                v[3] += bias[col + 3] + rv.w;
            } else if (EPI == 2) {
                #pragma unroll
                for (int j = 0; j < 4; ++j) {
                    float t = v[j] + bias[col + j];
                    v[j] = 0.5f * t * (1.0f + erff(t * 0.70710678118654752f));
                }
            }
            float4 o = {v[0], v[1], v[2], v[3]};
            *reinterpret_cast<float4*>(C + (size_t)row * N + col) = o;
        }
    }
}

// ---------------- banded attention: one warp per (b,h,q) ----------------
// qkv layout: row token (b*T+t) has [q(512) | k(512) | v(512)]; head h at offset h*64.
__global__ void attn_kernel(const float* __restrict__ qkv,
                            float* __restrict__ ctx,
                            const int* __restrict__ csp,
                            int T) {
    __shared__ float sc[4][272];
    const int cs   = min(*csp, 135);
    const int warp = threadIdx.x >> 5;
    const int lane = threadIdx.x & 31;
    const int gq = blockIdx.x * 4 + warp;   // over B*H*T
    const int t  = gq % T;
    const int bh = gq / T;
    const int h  = bh & (NHEAD - 1);
    const int b  = bh >> 3;

    const size_t rowbase = (size_t)(b * T) * (3 * DIM);
    const float* qp = qkv + rowbase + (size_t)t * (3 * DIM) + h * HDIM;
    const float2 qv = *reinterpret_cast<const float2*>(qp + 2 * lane);

    const int jlo = max(t - cs, 0);
    const int jhi = min(t + cs, T - 1);
    const float scale = 0.125f;   // 1/sqrt(64)

    // pass 1: scores + max
    float mx = -INFINITY;
    for (int j = jlo; j <= jhi; ++j) {
        const float2 kk = *reinterpret_cast<const float2*>(
            qkv + rowbase + (size_t)j * (3 * DIM) + DIM + h * HDIM + 2 * lane);
        float s = qv.x * kk.x + qv.y * kk.y;
        #pragma unroll
        for (int off = 16; off > 0; off >>= 1)
            s += __shfl_xor_sync(0xFFFFFFFFu, s, off);
        s *= scale;
        mx = fmaxf(mx, s);
        if (lane == 0) sc[warp][j - jlo] = s;
    }
    __syncwarp();

    // pass 2: exp + sum
    const int n = jhi - jlo + 1;
    float sum = 0.0f;
    for (int i = lane; i < n; i += 32) {
        const float p = __expf(sc[warp][i] - mx);
        sc[warp][i] = p;
        sum += p;
    }
    #pragma unroll
    for (int off = 16; off > 0; off >>= 1)
        sum += __shfl_xor_sync(0xFFFFFFFFu, sum, off);
    const float inv = 1.0f / sum;
    __syncwarp();

    // pass 3: weighted V sum (each lane owns 2 dims)
    float2 acc = {0.0f, 0.0f};
    for (int j = jlo; j <= jhi; ++j) {
        const float p = sc[warp][j - jlo];
        const float2 vv = *reinterpret_cast<const float2*>(
            qkv + rowbase + (size_t)j * (3 * DIM) + 2 * DIM + h * HDIM + 2 * lane);
        acc.x = fmaf(p, vv.x, acc.x);
        acc.y = fmaf(p, vv.y, acc.y);
    }
    float2 o = {acc.x * inv, acc.y * inv};
    *reinterpret_cast<float2*>(
        ctx + (size_t)(b * T + t) * DIM + h * HDIM + 2 * lane) = o;
}

// ---------------- launcher ----------------
extern "C" void kernel_launch(void* const* d_in, const int* in_sizes, int n_in,
                              void* d_out, int out_size) {
    const float* x       = (const float*)d_in[0];
    const float* norm1_w = (const float*)d_in[1];
    const float* norm2_w = (const float*)d_in[2];
    const float* w_qkv   = (const float*)d_in[3];
    const float* w_out   = (const float*)d_in[4];
    const float* b_out   = (const float*)d_in[5];
    const float* w1      = (const float*)d_in[6];
    const float* b1      = (const float*)d_in[7];
    const float* w2      = (const float*)d_in[8];
    const float* b2      = (const float*)d_in[9];
    const int*   cs      = (const int*)d_in[10];
    float*       out     = (float*)d_out;

    const int BT = in_sizes[0] / DIM;   // B*T = 8192
    const int T  = T_SEQ;

    float *xn, *qkv, *ctx, *x1, *hbuf;
    cudaGetSymbolAddress((void**)&xn,   g_xn);
    cudaGetSymbolAddress((void**)&qkv,  g_qkv);
    cudaGetSymbolAddress((void**)&ctx,  g_ctx);
    cudaGetSymbolAddress((void**)&x1,   g_x1);
    cudaGetSymbolAddress((void**)&hbuf, g_h);

    // 1. xn = rmsnorm(x, norm1_w)
    rmsnorm_kernel<<<BT, 128>>>(x, norm1_w, xn);
    // 2. qkv = xn @ w_qkv
    gemm_kernel<0><<<dim3((3 * DIM) / 128, BT / 128), 256>>>(
        xn, w_qkv, nullptr, nullptr, qkv, BT, 3 * DIM, DIM);
    // 3. banded attention -> ctx
    attn_kernel<<<(BT * NHEAD) / 4, 128>>>(qkv, ctx, cs, T);
    // 4. x1 = x + ctx @ w_out + b_out
    gemm_kernel<1><<<dim3(DIM / 128, BT / 128), 256>>>(
        ctx, w_out, b_out, x, x1, BT, DIM, DIM);
    // 5. xn = rmsnorm(x1, norm2_w)
    rmsnorm_kernel<<<BT, 128>>>(x1, norm2_w, xn);
    // 6. h = gelu(xn @ w1 + b1)
    gemm_kernel<2><<<dim3(FFN_DIM / 128, BT / 128), 256>>>(
        xn, w1, b1, nullptr, hbuf, BT, FFN_DIM, DIM);
    // 7. out = x1 + h @ w2 + b2
    gemm_kernel<1><<<dim3(DIM / 128, BT / 128), 256>>>(
        hbuf, w2, b2, x1, out, BT, DIM, FFN_DIM);
}

// round 4
// speedup vs baseline: 1.4318x; 1.4318x over previous
#include <cuda_runtime.h>
#include <cuda_bf16.h>
#include <math.h>
#include <stdint.h>

// Problem shape (fixed by the dataset): B=4, T=2048, D=512, H=8, Hd=64, FFN=2048
#define T_SEQ   2048
#define DIM     512
#define NHEAD   8
#define HDIM    64
#define FFN_DIM 2048
#define MAX_BT  8192

// ======================= helpers =======================
__device__ __forceinline__ uint32_t smem_u32(const void* p) {
    uint32_t a;
    asm("{ .reg .u64 t; cvta.to.shared.u64 t, %1; cvt.u32.u64 %0, t; }" : "=r"(a) : "l"(p));
    return a;
}
__device__ __forceinline__ void cp16(uint32_t s, const void* g) {
    asm volatile("cp.async.ca.shared.global [%0], [%1], 16;" :: "r"(s), "l"(g));
}
#define CP_COMMIT() asm volatile("cp.async.commit_group;" ::: "memory")
#define CP_WAIT1()  asm volatile("cp.async.wait_group 1;" ::: "memory")

__device__ __forceinline__ void ldsm4(uint32_t* r, uint32_t addr) {
    asm volatile("ldmatrix.sync.aligned.m8n8.x4.shared.b16 {%0,%1,%2,%3}, [%4];"
        : "=r"(r[0]), "=r"(r[1]), "=r"(r[2]), "=r"(r[3]) : "r"(addr));
}
__device__ __forceinline__ void mma_bf16(float* c, const uint32_t* a, const uint32_t* b) {
    asm volatile(
        "mma.sync.aligned.m16n8k16.row.col.f32.bf16.bf16.f32 "
        "{%0,%1,%2,%3}, {%4,%5,%6,%7}, {%8,%9}, {%0,%1,%2,%3};"
        : "+f"(c[0]), "+f"(c[1]), "+f"(c[2]), "+f"(c[3])
        : "r"(a[0]), "r"(a[1]), "r"(a[2]), "r"(a[3]), "r"(b[0]), "r"(b[1]));
}
__device__ __forceinline__ void split2(float f, __nv_bfloat16& h, __nv_bfloat16& l) {
    h = __float2bfloat16(f);
    l = __float2bfloat16(f - __bfloat162float(h));
}

// ======================= scratch =======================
__device__ __nv_bfloat16 g_wqkvT_h[3 * DIM * DIM], g_wqkvT_l[3 * DIM * DIM];
__device__ __nv_bfloat16 g_woutT_h[DIM * DIM],     g_woutT_l[DIM * DIM];
__device__ __nv_bfloat16 g_w1T_h[FFN_DIM * DIM],   g_w1T_l[FFN_DIM * DIM];
__device__ __nv_bfloat16 g_w2T_h[DIM * FFN_DIM],   g_w2T_l[DIM * FFN_DIM];
__device__ __nv_bfloat16 g_xn_h[MAX_BT * DIM],     g_xn_l[MAX_BT * DIM];
__device__ __nv_bfloat16 g_ctx_h[MAX_BT * DIM],    g_ctx_l[MAX_BT * DIM];
__device__ __nv_bfloat16 g_hh[MAX_BT * FFN_DIM],   g_hl[MAX_BT * FFN_DIM];
__device__ float g_qkv[MAX_BT * 3 * DIM];
__device__ float g_x1[MAX_BT * DIM];

// ======================= weight prep: W[K][N] -> WT hi/lo [N][K] =======================
__global__ void wprep_kernel(const float* __restrict__ W,
                             __nv_bfloat16* __restrict__ Th,
                             __nv_bfloat16* __restrict__ Tl,
                             int K, int N) {
    __shared__ float t[32][33];
    const int n0 = blockIdx.x * 32, k0 = blockIdx.y * 32;
    const int tx = threadIdx.x, ty = threadIdx.y;
    #pragma unroll
    for (int i = 0; i < 4; ++i)
        t[ty + i * 8][tx] = W[(size_t)(k0 + ty + i * 8) * N + n0 + tx];
    __syncthreads();
    #pragma unroll
    for (int i = 0; i < 4; ++i) {
        const float v = t[tx][ty + i * 8];
        __nv_bfloat16 h, l;
        split2(v, h, l);
        const size_t o = (size_t)(n0 + ty + i * 8) * K + k0 + tx;
        Th[o] = h;
        Tl[o] = l;
    }
}

// ======================= rmsnorm -> bf16 hi/lo =======================
__global__ void rmsnorm_split_kernel(const float* __restrict__ x,
                                     const float* __restrict__ w,
                                     __nv_bfloat16* __restrict__ yh,
                                     __nv_bfloat16* __restrict__ yl) {
    const int row = blockIdx.x;
    const int tid = threadIdx.x;  // 128
    const float4 v = reinterpret_cast<const float4*>(x + (size_t)row * DIM)[tid];
    float ss = v.x * v.x + v.y * v.y + v.z * v.z + v.w * v.w;
    #pragma unroll
    for (int off = 16; off > 0; off >>= 1)
        ss += __shfl_xor_sync(0xFFFFFFFFu, ss, off);
    __shared__ float red[4];
    const int warp = tid >> 5, lane = tid & 31;
    if (lane == 0) red[warp] = ss;
    __syncthreads();
    const float r = rsqrtf((red[0] + red[1] + red[2] + red[3]) * (1.0f / DIM) + 1e-6f);
    const float4 wv = reinterpret_cast<const float4*>(w)[tid];
    float o[4] = {v.x * r * wv.x, v.y * r * wv.y, v.z * r * wv.z, v.w * r * wv.w};
    __nv_bfloat16 h[4], l[4];
    #pragma unroll
    for (int j = 0; j < 4; ++j) split2(o[j], h[j], l[j]);
    const size_t e = (size_t)row * DIM + tid * 4;
    *reinterpret_cast<__nv_bfloat162*>(yh + e)     = {h[0], h[1]};
    *reinterpret_cast<__nv_bfloat162*>(yh + e + 2) = {h[2], h[3]};
    *reinterpret_cast<__nv_bfloat162*>(yl + e)     = {l[0], l[1]};
    *reinterpret_cast<__nv_bfloat162*>(yl + e + 2) = {l[2], l[3]};
}

// ======================= mma.sync GEMM =======================
// C[M,N] = sum_k A[M,K]*B^T[N,K]; A,B pre-split bf16 hi/lo, K-major rows.
// 128x128 block tile, 8 warps (64x32 each), K-slab 32, cp.async double buffer.
// SMEM row stride 40 bf16 (80B) -> ldmatrix conflict-free.
// EPI: 0 = fp32 C; 1 = +bias +resid -> fp32 C; 2 = +bias, gelu -> bf16 hi/lo
#define PADK   40
#define MATB   (128 * PADK * 2)      // 10240 bytes per matrix tile
#define STAGEB (4 * MATB)            // Ah, Al, Bh, Bl
#define GEMM_DSMEM (2 * STAGEB)      // 81920

template <int EPI>
__global__ __launch_bounds__(256, 1)
void gemm_mma(const __nv_bfloat16* __restrict__ Ahi, const __nv_bfloat16* __restrict__ Alo,
              const __nv_bfloat16* __restrict__ Bhi, const __nv_bfloat16* __restrict__ Blo,
              const float* __restrict__ bias, const float* __restrict__ R,
              float* __restrict__ C,
              __nv_bfloat16* __restrict__ Chi, __nv_bfloat16* __restrict__ Clo,
              int M, int N, int K) {
    extern __shared__ char dsm[];
    const uint32_t sm0 = smem_u32(dsm);
    const int tid = threadIdx.x;
    const int wid = tid >> 5;
    const int lane = tid & 31;
    const int wm = wid & 1;             // 0..1 over M
    const int wn = wid >> 1;            // 0..3 over N
    const int bm = blockIdx.y * 128;
    const int bn = blockIdx.x * 128;

    // loader mapping: 512 16B-chunks per matrix tile, 2 per thread
    const int r0 = tid >> 1;                  // rows r0, r0+... idx scheme below
    (void)r0;

    const int NS = K / 32;

    // issue cp.async for slab s into stage (s&1)
    auto load_slab = [&](int s) {
        const uint32_t st = sm0 + (uint32_t)(s & 1) * STAGEB;
        const int k0 = s * 32;
        #pragma unroll
        for (int i = 0; i < 2; ++i) {
            const int idx = tid + i * 256;        // 0..511
            const int row = idx >> 2;             // 0..127
            const int c   = idx & 3;              // 0..3
            const uint32_t so = (uint32_t)(row * 80 + c * 16);
            const size_t gA = (size_t)(bm + row) * K + k0 + c * 8;
            const size_t gB = (size_t)(bn + row) * K + k0 + c * 8;
            cp16(st + 0 * MATB + so, Ahi + gA);
            cp16(st + 1 * MATB + so, Alo + gA);
            cp16(st + 2 * MATB + so, Bhi + gB);
            cp16(st + 3 * MATB + so, Blo + gB);
        }
    };

    float acc[4][4][4] = {};

    load_slab(0); CP_COMMIT();
    if (NS > 1) { load_slab(1); }
    CP_COMMIT();

    // ldmatrix base offsets (within-tile), fixed per thread
    const uint32_t aRow = (uint32_t)(wm * 64 + (lane & 15));
    const uint32_t aKo  = (uint32_t)((lane >> 4) * 8);
    const uint32_t bRow = (uint32_t)(wn * 32 + (lane & 7) + ((lane >> 4) << 3));
    const uint32_t bKo  = (uint32_t)(((lane >> 3) & 1) * 8);

    for (int s = 0; s < NS; ++s) {
        CP_WAIT1();
        __syncthreads();
        const uint32_t st = sm0 + (uint32_t)(s & 1) * STAGEB;

        #pragma unroll
        for (int kk = 0; kk < 32; kk += 16) {
            uint32_t ah[4][4], al[4][4], bh[2][4], bl[2][4];
            #pragma unroll
            for (int mi = 0; mi < 4; ++mi) {
                const uint32_t off = ((aRow + mi * 16) * PADK + kk + aKo) * 2;
                ldsm4(ah[mi], st + 0 * MATB + off);
                ldsm4(al[mi], st + 1 * MATB + off);
            }
            #pragma unroll
            for (int g = 0; g < 2; ++g) {
                const uint32_t off = ((bRow + g * 16) * PADK + kk + bKo) * 2;
                ldsm4(bh[g], st + 2 * MATB + off);
                ldsm4(bl[g], st + 3 * MATB + off);
            }
            #pragma unroll
            for (int mi = 0; mi < 4; ++mi) {
                #pragma unroll
                for (int ni = 0; ni < 4; ++ni) {
                    const int g = ni >> 1, sub = (ni & 1) * 2;
                    mma_bf16(acc[mi][ni], ah[mi], &bh[g][sub]);
                    mma_bf16(acc[mi][ni], ah[mi], &bl[g][sub]);
                    mma_bf16(acc[mi][ni], al[mi], &bh[g][sub]);
                }
            }
        }
        __syncthreads();
        if (s + 2 < NS) load_slab(s + 2);
        CP_COMMIT();
    }

    // epilogue: acc -> gmem (thread holds pairs of consecutive cols)
    const int cbase = bn + wn * 32 + (lane & 3) * 2;
    const int rbase = bm + wm * 64 + (lane >> 2);
    #pragma unroll
    for (int mi = 0; mi < 4; ++mi) {
        #pragma unroll
        for (int ni = 0; ni < 4; ++ni) {
            const int col = cbase + ni * 8;
            #pragma unroll
            for (int half = 0; half < 2; ++half) {
                const int row = rbase + mi * 16 + half * 8;
                float v0 = acc[mi][ni][half * 2 + 0];
                float v1 = acc[mi][ni][half * 2 + 1];
                if (EPI == 0) {
                    *(float2*)(C + (size_t)row * N + col) = {v0, v1};
                } else if (EPI == 1) {
                    const float2 rv = *(const float2*)(R + (size_t)row * N + col);
                    v0 += bias[col]     + rv.x;
                    v1 += bias[col + 1] + rv.y;
                    *(float2*)(C + (size_t)row * N + col) = {v0, v1};
                } else {
                    float t0 = v0 + bias[col];
                    float t1 = v1 + bias[col + 1];
                    const float g0 = 0.5f * t0 * (1.0f + erff(t0 * 0.70710678118654752f));
                    const float g1 = 0.5f * t1 * (1.0f + erff(t1 * 0.70710678118654752f));
                    __nv_bfloat16 h0, l0, h1, l1;
                    split2(g0, h0, l0);
                    split2(g1, h1, l1);
                    const size_t e = (size_t)row * N + col;
                    *reinterpret_cast<__nv_bfloat162*>(Chi + e) = {h0, h1};
                    *reinterpret_cast<__nv_bfloat162*>(Clo + e) = {l0, l1};
                }
            }
        }
    }
}

// ======================= banded attention (q-tiled, SMEM K/V) =======================
// grid (T/64, H, B), block 256. K/V band for 64 queries cached in SMEM.
#define ATT_KBYTES (192 * 64 * 4)
#define ATT_DSMEM  (2 * ATT_KBYTES + 8 * 136 * 4)

__global__ __launch_bounds__(256, 1)
void attn_kernel(const float* __restrict__ qkv,
                 __nv_bfloat16* __restrict__ ctx_h,
                 __nv_bfloat16* __restrict__ ctx_l,
                 const int* __restrict__ csp, int T) {
    extern __shared__ char dsm[];
    float* Ks = (float*)dsm;                       // [192][64]
    float* Vs = (float*)(dsm + ATT_KBYTES);        // [192][64]
    float* scb = (float*)(dsm + 2 * ATT_KBYTES);   // [8][136]

    const int cs = min(*csp, 64);
    const int tid = threadIdx.x;
    const int wid = tid >> 5;
    const int lane = tid & 31;
    const int q0 = blockIdx.x * 64;
    const int h = blockIdx.y;
    const int b = blockIdx.z;

    const int jlo = max(q0 - cs, 0);
    const int jhi = min(q0 + 63 + cs, T - 1);
    const int nk = jhi - jlo + 1;

    for (int i = tid; i < nk * 16; i += 256) {
        const int row = i >> 4, c = i & 15;
        const float4* src = (const float4*)(qkv + (size_t)(b * T + jlo + row) * (3 * DIM) + h * HDIM);
        ((float4*)Ks)[row * 16 + c] = src[c + 128];   // +DIM floats
        ((float4*)Vs)[row * 16 + c] = src[c + 256];   // +2*DIM floats
    }
    __syncthreads();

    float* sc = scb + wid * 136;
    const float scale = 0.125f;  // 1/sqrt(64)

    for (int qi = 0; qi < 8; ++qi) {
        const int t = q0 + wid * 8 + qi;
        const float2 qv = *(const float2*)(qkv + (size_t)(b * T + t) * (3 * DIM) + h * HDIM + 2 * lane);
        const int jloq = max(t - cs, 0);
        const int jhiq = min(t + cs, T - 1);
        const int base = jloq - jlo;
        const int n = jhiq - jloq + 1;

        float mx = -INFINITY;
        for (int j = 0; j < n; ++j) {
            const float2 kk = *(const float2*)(Ks + (base + j) * 64 + 2 * lane);
            float s = qv.x * kk.x + qv.y * kk.y;
            #pragma unroll
            for (int off = 16; off > 0; off >>= 1)
                s += __shfl_xor_sync(0xFFFFFFFFu, s, off);
            s *= scale;
            mx = fmaxf(mx, s);
            if (lane == 0) sc[j] = s;
        }
        __syncwarp();

        float sum = 0.0f;
        for (int i = lane; i < n; i += 32) {
            const float p = __expf(sc[i] - mx);
            sc[i] = p;
            sum += p;
        }
        #pragma unroll
        for (int off = 16; off > 0; off >>= 1)
            sum += __shfl_xor_sync(0xFFFFFFFFu, sum, off);
        const float inv = 1.0f / sum;
        __syncwarp();

        float2 acc = {0.0f, 0.0f};
        for (int j = 0; j < n; ++j) {
            const float p = sc[j];
            const float2 vv = *(const float2*)(Vs + (base + j) * 64 + 2 * lane);
            acc.x = fmaf(p, vv.x, acc.x);
            acc.y = fmaf(p, vv.y, acc.y);
        }
        const float ox = acc.x * inv, oy = acc.y * inv;
        __nv_bfloat16 hx, lx, hy, ly;
        split2(ox, hx, lx);
        split2(oy, hy, ly);
        const size_t e = (size_t)(b * T + t) * DIM + h * HDIM + 2 * lane;
        *reinterpret_cast<__nv_bfloat162*>(ctx_h + e) = {hx, hy};
        *reinterpret_cast<__nv_bfloat162*>(ctx_l + e) = {lx, ly};
        __syncwarp();
    }
}

// ======================= launcher =======================
extern "C" void kernel_launch(void* const* d_in, const int* in_sizes, int n_in,
                              void* d_out, int out_size) {
    const float* x       = (const float*)d_in[0];
    const float* norm1_w = (const float*)d_in[1];
    const float* norm2_w = (const float*)d_in[2];
    const float* w_qkv   = (const float*)d_in[3];
    const float* w_out   = (const float*)d_in[4];
    const float* b_out   = (const float*)d_in[5];
    const float* w1      = (const float*)d_in[6];
    const float* b1      = (const float*)d_in[7];
    const float* w2      = (const float*)d_in[8];
    const float* b2      = (const float*)d_in[9];
    const int*   cs      = (const int*)d_in[10];
    float*       out     = (float*)d_out;

    const int BT = in_sizes[0] / DIM;   // 8192
    const int T  = T_SEQ;
    const int B  = BT / T;

    __nv_bfloat16 *wqkvTh, *wqkvTl, *woutTh, *woutTl, *w1Th, *w1Tl, *w2Th, *w2Tl;
    __nv_bfloat16 *xnh, *xnl, *ctxh, *ctxl, *hh, *hl;
    float *qkv, *x1;
    cudaGetSymbolAddress((void**)&wqkvTh, g_wqkvT_h);
    cudaGetSymbolAddress((void**)&wqkvTl, g_wqkvT_l);
    cudaGetSymbolAddress((void**)&woutTh, g_woutT_h);
    cudaGetSymbolAddress((void**)&woutTl, g_woutT_l);
    cudaGetSymbolAddress((void**)&w1Th,   g_w1T_h);
    cudaGetSymbolAddress((void**)&w1Tl,   g_w1T_l);
    cudaGetSymbolAddress((void**)&w2Th,   g_w2T_h);
    cudaGetSymbolAddress((void**)&w2Tl,   g_w2T_l);
    cudaGetSymbolAddress((void**)&xnh,    g_xn_h);
    cudaGetSymbolAddress((void**)&xnl,    g_xn_l);
    cudaGetSymbolAddress((void**)&ctxh,   g_ctx_h);
    cudaGetSymbolAddress((void**)&ctxl,   g_ctx_l);
    cudaGetSymbolAddress((void**)&hh,     g_hh);
    cudaGetSymbolAddress((void**)&hl,     g_hl);
    cudaGetSymbolAddress((void**)&qkv,    g_qkv);
    cudaGetSymbolAddress((void**)&x1,     g_x1);

    cudaFuncSetAttribute(gemm_mma<0>, cudaFuncAttributeMaxDynamicSharedMemorySize, GEMM_DSMEM);
    cudaFuncSetAttribute(gemm_mma<1>, cudaFuncAttributeMaxDynamicSharedMemorySize, GEMM_DSMEM);
    cudaFuncSetAttribute(gemm_mma<2>, cudaFuncAttributeMaxDynamicSharedMemorySize, GEMM_DSMEM);
    cudaFuncSetAttribute(attn_kernel, cudaFuncAttributeMaxDynamicSharedMemorySize, ATT_DSMEM);

    const dim3 wb(32, 8);
    wprep_kernel<<<dim3((3 * DIM) / 32, DIM / 32), wb>>>(w_qkv, wqkvTh, wqkvTl, DIM, 3 * DIM);
    wprep_kernel<<<dim3(DIM / 32, DIM / 32), wb>>>(w_out, woutTh, woutTl, DIM, DIM);
    wprep_kernel<<<dim3(FFN_DIM / 32, DIM / 32), wb>>>(w1, w1Th, w1Tl, DIM, FFN_DIM);
    wprep_kernel<<<dim3(DIM / 32, FFN_DIM / 32), wb>>>(w2, w2Th, w2Tl, FFN_DIM, DIM);

    // 1. xn = rmsnorm(x, norm1_w) -> hi/lo
    rmsnorm_split_kernel<<<BT, 128>>>(x, norm1_w, xnh, xnl);
    // 2. qkv = xn @ w_qkv (fp32 out)
    gemm_mma<0><<<dim3((3 * DIM) / 128, BT / 128), 256, GEMM_DSMEM>>>(
        xnh, xnl, wqkvTh, wqkvTl, nullptr, nullptr, qkv, nullptr, nullptr, BT, 3 * DIM, DIM);
    // 3. banded attention -> ctx hi/lo
    attn_kernel<<<dim3(T / 64, NHEAD, B), 256, ATT_DSMEM>>>(qkv, ctxh, ctxl, cs, T);
    // 4. x1 = x + ctx @ w_out + b_out
    gemm_mma<1><<<dim3(DIM / 128, BT / 128), 256, GEMM_DSMEM>>>(
        ctxh, ctxl, woutTh, woutTl, b_out, x, x1, nullptr, nullptr, BT, DIM, DIM);
    // 5. xn = rmsnorm(x1, norm2_w) -> hi/lo
    rmsnorm_split_kernel<<<BT, 128>>>(x1, norm2_w, xnh, xnl);
    // 6. h = gelu(xn @ w1 + b1) -> hi/lo bf16
    gemm_mma<2><<<dim3(FFN_DIM / 128, BT / 128), 256, GEMM_DSMEM>>>(
        xnh, xnl, w1Th, w1Tl, b1, nullptr, nullptr, hh, hl, BT, FFN_DIM, DIM);
    // 7. out = x1 + h @ w2 + b2
    gemm_mma<1><<<dim3(DIM / 128, BT / 128), 256, GEMM_DSMEM>>>(
        hh, hl, w2Th, w2Tl, b2, x1, out, nullptr, nullptr, BT, DIM, FFN_DIM);
}